// round 2
// baseline (speedup 1.0000x reference)
#include <cuda_runtime.h>

#define T_TOK 2048
#define SDIM  1024
#define EDIM  1024
#define HID   150
#define MAXW  10
#define TM    16      // tokens per MLP block
#define NW    16      // warps per MLP block (512 threads)

__device__ float g_attns[T_TOK];

// ---------------------------------------------------------------------------
// Kernel 1: fused 3-layer MLP -> per-token scalar score
// grid = 2048/16 = 128 blocks (single balanced wave on 148 SMs), 512 threads.
// Each warp computes 2 hidden rows x 16 tokens per group with double-buffered
// weight loads; warp-butterfly reduction over K.
// ---------------------------------------------------------------------------
__global__ __launch_bounds__(512) void mlp_kernel(
    const float* __restrict__ states,
    const float* __restrict__ w1, const float* __restrict__ b1,
    const float* __restrict__ w2, const float* __restrict__ b2,
    const float* __restrict__ w3, const float* __restrict__ b3)
{
    __shared__ float4 As4[TM][SDIM / 4];      // 64 KB
    __shared__ float  h1s[TM][HID + 2];
    __shared__ float  h2s[TM][HID + 2];
    __shared__ float  b1s[HID + 2], b2s[HID + 2];

    const int tid  = threadIdx.x;
    const int lane = tid & 31;
    const int w    = tid >> 5;
    const int t0   = blockIdx.x * TM;

    // stage 16 token states + biases into SMEM
    const float4* st4 = (const float4*)states;
    for (int idx = tid; idx < TM * (SDIM / 4); idx += 512) {
        int t = idx >> 8, k = idx & 255;
        As4[t][k] = st4[(size_t)(t0 + t) * (SDIM / 4) + k];
    }
    if (tid < HID) { b1s[tid] = b1[tid]; b2s[tid] = b2[tid]; }
    __syncthreads();

    // ---------------- layer 1: h1 = relu(states @ w1^T + b1) ----------------
    for (int g = w; g < HID / 2; g += NW) {         // 75 groups of 2 rows
        const int j0 = g * 2;
        const float4* wr0 = (const float4*)(w1 + (size_t)(j0 + 0) * SDIM);
        const float4* wr1 = (const float4*)(w1 + (size_t)(j0 + 1) * SDIM);

        float acc0[TM], acc1[TM];
        #pragma unroll
        for (int t = 0; t < TM; t++) { acc0[t] = 0.f; acc1[t] = 0.f; }

        float4 wa = wr0[lane], wb = wr1[lane];      // prefetch
        #pragma unroll
        for (int ci = 0; ci < 8; ci++) {
            const float4 cw0 = wa, cw1 = wb;
            if (ci < 7) { wa = wr0[lane + (ci + 1) * 32]; wb = wr1[lane + (ci + 1) * 32]; }
            const int c = lane + ci * 32;
            #pragma unroll
            for (int t = 0; t < TM; t++) {
                float4 av = As4[t][c];
                acc0[t] += cw0.x * av.x + cw0.y * av.y + cw0.z * av.z + cw0.w * av.w;
                acc1[t] += cw1.x * av.x + cw1.y * av.y + cw1.z * av.z + cw1.w * av.w;
            }
        }
        #pragma unroll
        for (int off = 16; off; off >>= 1)
            #pragma unroll
            for (int t = 0; t < TM; t++) {
                acc0[t] += __shfl_xor_sync(0xffffffffu, acc0[t], off);
                acc1[t] += __shfl_xor_sync(0xffffffffu, acc1[t], off);
            }
        // lane l stores slot (u = l>>4 selects row, t = l&15 selects token)
        float v = 0.f;
        #pragma unroll
        for (int t = 0; t < TM; t++)
            if ((lane & 15) == t) v = (lane < 16) ? acc0[t] : acc1[t];
        const int ju = j0 + (lane >> 4);
        h1s[lane & 15][ju] = fmaxf(v + b1s[ju], 0.f);
    }
    __syncthreads();

    // ---------------- layer 2: h2 = relu(h1 @ w2^T + b2) --------------------
    for (int g = w; g < HID / 2; g += NW) {
        const int j0 = g * 2;
        const float* r0 = w2 + (size_t)(j0 + 0) * HID;
        const float* r1 = w2 + (size_t)(j0 + 1) * HID;

        float acc0[TM], acc1[TM];
        #pragma unroll
        for (int t = 0; t < TM; t++) { acc0[t] = 0.f; acc1[t] = 0.f; }

        for (int kk = lane; kk < HID; kk += 32) {
            const float wv0 = r0[kk], wv1 = r1[kk];
            #pragma unroll
            for (int t = 0; t < TM; t++) {
                float hv = h1s[t][kk];
                acc0[t] += wv0 * hv;
                acc1[t] += wv1 * hv;
            }
        }
        #pragma unroll
        for (int off = 16; off; off >>= 1)
            #pragma unroll
            for (int t = 0; t < TM; t++) {
                acc0[t] += __shfl_xor_sync(0xffffffffu, acc0[t], off);
                acc1[t] += __shfl_xor_sync(0xffffffffu, acc1[t], off);
            }
        float v = 0.f;
        #pragma unroll
        for (int t = 0; t < TM; t++)
            if ((lane & 15) == t) v = (lane < 16) ? acc0[t] : acc1[t];
        const int ju = j0 + (lane >> 4);
        h2s[lane & 15][ju] = fmaxf(v + b2s[ju], 0.f);
    }
    __syncthreads();

    // ---------------- layer 3: attns = h2 @ w3^T + b3 -----------------------
    if (w == 0) {
        float acc[TM];
        #pragma unroll
        for (int t = 0; t < TM; t++) acc[t] = 0.f;
        for (int kk = lane; kk < HID; kk += 32) {
            const float wv = w3[kk];
            #pragma unroll
            for (int t = 0; t < TM; t++) acc[t] += wv * h2s[t][kk];
        }
        #pragma unroll
        for (int off = 16; off; off >>= 1)
            #pragma unroll
            for (int t = 0; t < TM; t++)
                acc[t] += __shfl_xor_sync(0xffffffffu, acc[t], off);
        float v = 0.f;
        #pragma unroll
        for (int t = 0; t < TM; t++)
            if (lane == t) v = acc[t];
        if (lane < TM) g_attns[t0 + lane] = v + b3[0];
    }
}

// ---------------------------------------------------------------------------
// Kernel 2: span assembly. One block per start r; all widths n=1..10 share
// a running softmax numerator. Embed rows prefetched via cp.async so all
// global-load latency is front-loaded; streaming stores (__stcs) keep the
// 251MB output stream from evicting the hot embeds/states in L2.
// ---------------------------------------------------------------------------
__global__ __launch_bounds__(256) void assemble_kernel(
    const float* __restrict__ embeds,
    const float* __restrict__ states,
    float* __restrict__ out)
{
    const int r    = blockIdx.x;
    const int tid  = threadIdx.x;
    const int nmax = min(MAXW, T_TOK - r);

    __shared__ __align__(16) float se[MAXW][EDIM];   // 40 KB
    __shared__ float ws[MAXW];
    __shared__ float invden[MAXW];

    // async-prefetch the nmax embed rows into SMEM (16B per thread per row)
    {
        unsigned smem_addr = (unsigned)__cvta_generic_to_shared(&se[0][tid * 4]);
        const float4* src = (const float4*)embeds + (size_t)r * 256 + tid;
        #pragma unroll
        for (int i = 0; i < MAXW; i++) {
            if (i < nmax) {
                asm volatile("cp.async.cg.shared.global [%0], [%1], 16;\n"
                             :: "r"(smem_addr + i * (EDIM * 4)), "l"(src + i * 256));
            }
        }
        asm volatile("cp.async.commit_group;\n" ::: "memory");
    }

    // softmax prefix (running denominator) — single thread, overlapped with
    // the async loads above
    if (tid == 0) {
        float a[MAXW];
        float m = -1e30f;
        for (int i = 0; i < nmax; i++) {
            a[i] = g_attns[r + i];
            m = fmaxf(m, a[i]);
        }
        float den = 0.f;
        for (int i = 0; i < nmax; i++) {
            float e = __expf(a[i] - m);
            ws[i] = e;
            den += e;
            invden[i] = 1.0f / den;
        }
    }
    asm volatile("cp.async.wait_group 0;\n" ::: "memory");
    __syncthreads();

    const float4* st4  = (const float4*)states;
    float4*       out4 = (float4*)out;

    const float4 s0 = st4[r * 256 + tid];
    float4 num = make_float4(0.f, 0.f, 0.f, 0.f);

    #pragma unroll
    for (int i = 0; i < MAXW; i++) {
        if (i < nmax) {
            const float  wv = ws[i];
            const float4 e  = ((const float4*)se[i])[tid];
            num.x += wv * e.x; num.y += wv * e.y;
            num.z += wv * e.z; num.w += wv * e.w;

            // section offset for width n=i+1: (n-1)*2049 - n(n-1)/2
            const int row  = i * (T_TOK + 1) - ((i + 1) * i) / 2 + r;
            const int base = row * 768;                // 3072 floats / 4

            const float4 send = st4[(r + i) * 256 + tid];
            const float  id   = invden[i];
            __stcs(&out4[base + tid],       s0);
            __stcs(&out4[base + 256 + tid], send);
            __stcs(&out4[base + 512 + tid],
                   make_float4(num.x * id, num.y * id, num.z * id, num.w * id));
        }
    }
}

// ---------------------------------------------------------------------------
extern "C" void kernel_launch(void* const* d_in, const int* in_sizes, int n_in,
                              void* d_out, int out_size) {
    const float* embeds = (const float*)d_in[0];
    const float* states = (const float*)d_in[1];
    const float* w1     = (const float*)d_in[2];
    const float* b1     = (const float*)d_in[3];
    const float* w2     = (const float*)d_in[4];
    const float* b2     = (const float*)d_in[5];
    const float* w3     = (const float*)d_in[6];
    const float* b3     = (const float*)d_in[7];
    float* out = (float*)d_out;

    mlp_kernel<<<T_TOK / TM, 512>>>(states, w1, b1, w2, b2, w3, b3);
    assemble_kernel<<<T_TOK, 256>>>(embeds, states, out);
}

// round 3
// speedup vs baseline: 1.9623x; 1.9623x over previous
#include <cuda_runtime.h>

#define T_TOK 2048
#define SDIM  1024
#define EDIM  1024
#define HID   150
#define MAXW  10
#define TM    16      // tokens per MLP block
#define NW    8       // warps per MLP block (256 threads -> no reg spills)

__device__ float g_attns[T_TOK];

// ---------------------------------------------------------------------------
// Kernel 1: fused 3-layer MLP -> per-token scalar score
// grid = 2048/16 = 128 blocks (one block per SM), 256 threads.
// Each warp computes 2 hidden rows x 16 tokens per group with one-group-ahead
// register prefetch of w1; warp-butterfly reduction over K.
// 256 threads => up to 255 regs/thread: 32 accumulators live comfortably.
// ---------------------------------------------------------------------------
__global__ __launch_bounds__(256) void mlp_kernel(
    const float* __restrict__ states,
    const float* __restrict__ w1, const float* __restrict__ b1,
    const float* __restrict__ w2, const float* __restrict__ b2,
    const float* __restrict__ w3, const float* __restrict__ b3)
{
    __shared__ float4 As4[TM][SDIM / 4];      // 64 KB
    __shared__ float  h1s[TM][HID + 2];
    __shared__ float  h2s[TM][HID + 2];
    __shared__ float  b1s[HID + 2], b2s[HID + 2];

    const int tid  = threadIdx.x;
    const int lane = tid & 31;
    const int w    = tid >> 5;
    const int t0   = blockIdx.x * TM;

    // stage 16 token states + biases into SMEM (coalesced float4)
    const float4* st4 = (const float4*)states;
    for (int idx = tid; idx < TM * (SDIM / 4); idx += 256) {
        int t = idx >> 8, k = idx & 255;
        As4[t][k] = st4[(size_t)(t0 + t) * (SDIM / 4) + k];
    }
    if (tid < HID) { b1s[tid] = b1[tid]; b2s[tid] = b2[tid]; }
    __syncthreads();

    // ---------------- layer 1: h1 = relu(states @ w1^T + b1) ----------------
    for (int g = w; g < HID / 2; g += NW) {         // 75 groups of 2 rows
        const int j0 = g * 2;
        const float4* wr0 = (const float4*)(w1 + (size_t)(j0 + 0) * SDIM);
        const float4* wr1 = (const float4*)(w1 + (size_t)(j0 + 1) * SDIM);

        float acc0[TM], acc1[TM];
        #pragma unroll
        for (int t = 0; t < TM; t++) { acc0[t] = 0.f; acc1[t] = 0.f; }

        float4 wa = wr0[lane], wb = wr1[lane];      // prefetch
        #pragma unroll
        for (int ci = 0; ci < 8; ci++) {
            const float4 cw0 = wa, cw1 = wb;
            if (ci < 7) { wa = wr0[lane + (ci + 1) * 32]; wb = wr1[lane + (ci + 1) * 32]; }
            const int c = lane + ci * 32;
            #pragma unroll
            for (int t = 0; t < TM; t++) {
                float4 av = As4[t][c];
                acc0[t] += cw0.x * av.x + cw0.y * av.y + cw0.z * av.z + cw0.w * av.w;
                acc1[t] += cw1.x * av.x + cw1.y * av.y + cw1.z * av.z + cw1.w * av.w;
            }
        }
        #pragma unroll
        for (int off = 16; off; off >>= 1)
            #pragma unroll
            for (int t = 0; t < TM; t++) {
                acc0[t] += __shfl_xor_sync(0xffffffffu, acc0[t], off);
                acc1[t] += __shfl_xor_sync(0xffffffffu, acc1[t], off);
            }
        // lane l stores slot (row = l>>4, token = l&15)
        float v = 0.f;
        #pragma unroll
        for (int t = 0; t < TM; t++)
            if ((lane & 15) == t) v = (lane < 16) ? acc0[t] : acc1[t];
        const int ju = j0 + (lane >> 4);
        h1s[lane & 15][ju] = fmaxf(v + b1s[ju], 0.f);
    }
    __syncthreads();

    // ---------------- layer 2: h2 = relu(h1 @ w2^T + b2) --------------------
    for (int g = w; g < HID / 2; g += NW) {
        const int j0 = g * 2;
        const float* r0 = w2 + (size_t)(j0 + 0) * HID;
        const float* r1 = w2 + (size_t)(j0 + 1) * HID;

        float acc0[TM], acc1[TM];
        #pragma unroll
        for (int t = 0; t < TM; t++) { acc0[t] = 0.f; acc1[t] = 0.f; }

        for (int kk = lane; kk < HID; kk += 32) {
            const float wv0 = r0[kk], wv1 = r1[kk];
            #pragma unroll
            for (int t = 0; t < TM; t++) {
                float hv = h1s[t][kk];
                acc0[t] += wv0 * hv;
                acc1[t] += wv1 * hv;
            }
        }
        #pragma unroll
        for (int off = 16; off; off >>= 1)
            #pragma unroll
            for (int t = 0; t < TM; t++) {
                acc0[t] += __shfl_xor_sync(0xffffffffu, acc0[t], off);
                acc1[t] += __shfl_xor_sync(0xffffffffu, acc1[t], off);
            }
        float v = 0.f;
        #pragma unroll
        for (int t = 0; t < TM; t++)
            if ((lane & 15) == t) v = (lane < 16) ? acc0[t] : acc1[t];
        const int ju = j0 + (lane >> 4);
        h2s[lane & 15][ju] = fmaxf(v + b2s[ju], 0.f);
    }
    __syncthreads();

    // ---------------- layer 3: attns = h2 @ w3^T + b3 -----------------------
    if (w == 0) {
        float acc[TM];
        #pragma unroll
        for (int t = 0; t < TM; t++) acc[t] = 0.f;
        for (int kk = lane; kk < HID; kk += 32) {
            const float wv = w3[kk];
            #pragma unroll
            for (int t = 0; t < TM; t++) acc[t] += wv * h2s[t][kk];
        }
        #pragma unroll
        for (int off = 16; off; off >>= 1)
            #pragma unroll
            for (int t = 0; t < TM; t++)
                acc[t] += __shfl_xor_sync(0xffffffffu, acc[t], off);
        float v = 0.f;
        #pragma unroll
        for (int t = 0; t < TM; t++)
            if (lane == t) v = acc[t];
        if (lane < TM) g_attns[t0 + lane] = v + b3[0];
    }
}

// ---------------------------------------------------------------------------
// Kernel 2: span assembly (unchanged from R2 — measured at HBM write ceiling).
// One block per start r; widths n=1..10 share a running softmax numerator.
// ---------------------------------------------------------------------------
__global__ __launch_bounds__(256) void assemble_kernel(
    const float* __restrict__ embeds,
    const float* __restrict__ states,
    float* __restrict__ out)
{
    const int r    = blockIdx.x;
    const int tid  = threadIdx.x;
    const int nmax = min(MAXW, T_TOK - r);

    __shared__ __align__(16) float se[MAXW][EDIM];   // 40 KB
    __shared__ float ws[MAXW];
    __shared__ float invden[MAXW];

    // async-prefetch the nmax embed rows into SMEM
    {
        unsigned smem_addr = (unsigned)__cvta_generic_to_shared(&se[0][tid * 4]);
        const float4* src = (const float4*)embeds + (size_t)r * 256 + tid;
        #pragma unroll
        for (int i = 0; i < MAXW; i++) {
            if (i < nmax) {
                asm volatile("cp.async.cg.shared.global [%0], [%1], 16;\n"
                             :: "r"(smem_addr + i * (EDIM * 4)), "l"(src + i * 256));
            }
        }
        asm volatile("cp.async.commit_group;\n" ::: "memory");
    }

    // softmax prefix (running denominator), overlapped with async loads
    if (tid == 0) {
        float a[MAXW];
        float m = -1e30f;
        for (int i = 0; i < nmax; i++) {
            a[i] = g_attns[r + i];
            m = fmaxf(m, a[i]);
        }
        float den = 0.f;
        for (int i = 0; i < nmax; i++) {
            float e = __expf(a[i] - m);
            ws[i] = e;
            den += e;
            invden[i] = 1.0f / den;
        }
    }
    asm volatile("cp.async.wait_group 0;\n" ::: "memory");
    __syncthreads();

    const float4* st4  = (const float4*)states;
    float4*       out4 = (float4*)out;

    const float4 s0 = st4[r * 256 + tid];
    float4 num = make_float4(0.f, 0.f, 0.f, 0.f);

    #pragma unroll
    for (int i = 0; i < MAXW; i++) {
        if (i < nmax) {
            const float  wv = ws[i];
            const float4 e  = ((const float4*)se[i])[tid];
            num.x += wv * e.x; num.y += wv * e.y;
            num.z += wv * e.z; num.w += wv * e.w;

            // section offset for width n=i+1: (n-1)*2049 - n(n-1)/2
            const int row  = i * (T_TOK + 1) - ((i + 1) * i) / 2 + r;
            const int base = row * 768;                // 3072 floats / 4

            const float4 send = st4[(r + i) * 256 + tid];
            const float  id   = invden[i];
            __stcs(&out4[base + tid],       s0);
            __stcs(&out4[base + 256 + tid], send);
            __stcs(&out4[base + 512 + tid],
                   make_float4(num.x * id, num.y * id, num.z * id, num.w * id));
        }
    }
}

// ---------------------------------------------------------------------------
extern "C" void kernel_launch(void* const* d_in, const int* in_sizes, int n_in,
                              void* d_out, int out_size) {
    const float* embeds = (const float*)d_in[0];
    const float* states = (const float*)d_in[1];
    const float* w1     = (const float*)d_in[2];
    const float* b1     = (const float*)d_in[3];
    const float* w2     = (const float*)d_in[4];
    const float* b2     = (const float*)d_in[5];
    const float* w3     = (const float*)d_in[6];
    const float* b3     = (const float*)d_in[7];
    float* out = (float*)d_out;

    mlp_kernel<<<T_TOK / TM, 256>>>(states, w1, b1, w2, b2, w3, b3);
    assemble_kernel<<<T_TOK, 256>>>(embeds, states, out);
}

// round 5
// speedup vs baseline: 2.9735x; 1.5154x over previous
#include <cuda_runtime.h>

#define T_TOK 2048
#define SDIM  1024
#define EDIM  1024
#define HID   150
#define MAXW  10

#define TMM   16              // tokens per MLP block
#define MLPT  640             // MLP threads (20 warps)
#define KPAD  1032            // As row stride in FLOATS (1024 data + 8 pad)
#define HPAD  156             // h row stride in floats (624B, 16B-aligned)

__device__ float g_attns[T_TOK];

// packed 2xfp32 FMA: acc = w * a + acc (lanewise on .b64)
#define FMA2(acc, w_, a_) \
    asm volatile("fma.rn.f32x2 %0, %1, %2, %0;" : "+l"(acc) : "l"(w_), "l"(a_))

__device__ __forceinline__ float pairsum(unsigned long long v) {
    float lo, hi;
    asm("mov.b64 {%0,%1}, %2;" : "=f"(lo), "=f"(hi) : "l"(v));
    return lo + hi;
}

// ---------------------------------------------------------------------------
// Kernel 1: fused 3-layer MLP -> per-token scalar score.
// grid=128 blocks x 640 threads. Thread = (hidden unit j = tid>>2,
// token quarter q = tid&3 -> tokens {q, q+4, q+8, q+12}).
// Full-K accumulation per thread: NO cross-lane reductions.
// Inner loop uses fma.rn.f32x2 pairing over k-parity (operands naturally
// memory-adjacent -> no packing ops).
// ---------------------------------------------------------------------------
__global__ __launch_bounds__(MLPT) void mlp_kernel(
    const float* __restrict__ states,
    const float* __restrict__ w1, const float* __restrict__ b1,
    const float* __restrict__ w2, const float* __restrict__ b2,
    const float* __restrict__ w3, const float* __restrict__ b3)
{
    __shared__ __align__(16) float As[TMM][KPAD];    // ~66 KB
    __shared__ __align__(16) float h1s[TMM][HPAD];
    __shared__ __align__(16) float h2s[TMM][HPAD];

    const int tid = threadIdx.x;
    const int t0  = blockIdx.x * TMM;

    // stage 16 token states (coalesced float4 loads)
    for (int idx = tid; idx < TMM * (SDIM / 4); idx += MLPT) {
        const int t = idx >> 8, k4 = idx & 255;
        const float4 v = ((const float4*)states)[(size_t)(t0 + t) * 256 + k4];
        *(float4*)&As[t][k4 * 4] = v;
    }
    __syncthreads();

    const int q  = tid & 3;
    const int jj = tid >> 2;            // 0..159 (>=150 are shadow threads)
    const int jc = min(jj, HID - 1);

    const float* A0 = As[q + 0];
    const float* A1 = As[q + 4];
    const float* A2 = As[q + 8];
    const float* A3 = As[q + 12];

    // ---------------- layer 1: h1 = relu(states @ w1^T + b1) ----------------
    {
        const ulonglong2* wr = (const ulonglong2*)(w1 + (size_t)jc * SDIM);
        unsigned long long acc0 = 0, acc1 = 0, acc2 = 0, acc3 = 0;

        ulonglong2 wq = wr[0];
        #pragma unroll 4
        for (int k4 = 0; k4 < 256; ++k4) {
            const ulonglong2 cw = wq;
            if (k4 < 255) wq = wr[k4 + 1];
            const ulonglong2 a0 = *(const ulonglong2*)(A0 + 4 * k4);
            const ulonglong2 a1 = *(const ulonglong2*)(A1 + 4 * k4);
            const ulonglong2 a2 = *(const ulonglong2*)(A2 + 4 * k4);
            const ulonglong2 a3 = *(const ulonglong2*)(A3 + 4 * k4);
            FMA2(acc0, cw.x, a0.x); FMA2(acc0, cw.y, a0.y);
            FMA2(acc1, cw.x, a1.x); FMA2(acc1, cw.y, a1.y);
            FMA2(acc2, cw.x, a2.x); FMA2(acc2, cw.y, a2.y);
            FMA2(acc3, cw.x, a3.x); FMA2(acc3, cw.y, a3.y);
        }
        if (jj < HID) {
            const float bb = b1[jj];
            h1s[q + 0 ][jj] = fmaxf(pairsum(acc0) + bb, 0.f);
            h1s[q + 4 ][jj] = fmaxf(pairsum(acc1) + bb, 0.f);
            h1s[q + 8 ][jj] = fmaxf(pairsum(acc2) + bb, 0.f);
            h1s[q + 12][jj] = fmaxf(pairsum(acc3) + bb, 0.f);
        }
    }
    __syncthreads();

    // ---------------- layer 2: h2 = relu(h1 @ w2^T + b2) --------------------
    {
        const unsigned long long* wr2 =
            (const unsigned long long*)(w2 + (size_t)jc * HID);  // 75 pairs
        const float* B0 = h1s[q + 0];
        const float* B1 = h1s[q + 4];
        const float* B2 = h1s[q + 8];
        const float* B3 = h1s[q + 12];

        unsigned long long acc0 = 0, acc1 = 0, acc2 = 0, acc3 = 0;
        #pragma unroll 5
        for (int p = 0; p < HID / 2; ++p) {          // 75 k-pairs
            const unsigned long long wv = wr2[p];
            const unsigned long long a0 = *(const unsigned long long*)(B0 + 2 * p);
            const unsigned long long a1 = *(const unsigned long long*)(B1 + 2 * p);
            const unsigned long long a2 = *(const unsigned long long*)(B2 + 2 * p);
            const unsigned long long a3 = *(const unsigned long long*)(B3 + 2 * p);
            FMA2(acc0, wv, a0);
            FMA2(acc1, wv, a1);
            FMA2(acc2, wv, a2);
            FMA2(acc3, wv, a3);
        }
        if (jj < HID) {
            const float bb = b2[jj];
            h2s[q + 0 ][jj] = fmaxf(pairsum(acc0) + bb, 0.f);
            h2s[q + 4 ][jj] = fmaxf(pairsum(acc1) + bb, 0.f);
            h2s[q + 8 ][jj] = fmaxf(pairsum(acc2) + bb, 0.f);
            h2s[q + 12][jj] = fmaxf(pairsum(acc3) + bb, 0.f);
        }
    }
    __syncthreads();

    // ---------------- layer 3: attns = h2 @ w3^T + b3 -----------------------
    {
        const int wrp  = tid >> 5;
        const int lane = tid & 31;
        if (wrp < TMM) {                 // warp w handles token w
            float acc = 0.f;
            #pragma unroll
            for (int i = 0; i < 5; ++i) {
                const int kk = lane + 32 * i;
                if (kk < HID) acc += w3[kk] * h2s[wrp][kk];
            }
            #pragma unroll
            for (int off = 16; off; off >>= 1)
                acc += __shfl_xor_sync(0xffffffffu, acc, off);
            if (lane == 0) g_attns[t0 + wrp] = acc + b3[0];
        }
    }
}

// ---------------------------------------------------------------------------
// Kernel 2: span assembly (unchanged — at the HBM write floor across 3 rounds)
// ---------------------------------------------------------------------------
__global__ __launch_bounds__(256) void assemble_kernel(
    const float* __restrict__ embeds,
    const float* __restrict__ states,
    float* __restrict__ out)
{
    const int r    = blockIdx.x;
    const int tid  = threadIdx.x;
    const int nmax = min(MAXW, T_TOK - r);

    __shared__ __align__(16) float se[MAXW][EDIM];   // 40 KB
    __shared__ float ws[MAXW];
    __shared__ float invden[MAXW];

    {
        unsigned smem_addr = (unsigned)__cvta_generic_to_shared(&se[0][tid * 4]);
        const float4* src = (const float4*)embeds + (size_t)r * 256 + tid;
        #pragma unroll
        for (int i = 0; i < MAXW; i++) {
            if (i < nmax) {
                asm volatile("cp.async.cg.shared.global [%0], [%1], 16;\n"
                             :: "r"(smem_addr + i * (EDIM * 4)), "l"(src + i * 256));
            }
        }
        asm volatile("cp.async.commit_group;\n" ::: "memory");
    }

    if (tid == 0) {
        float a[MAXW];
        float m = -1e30f;
        for (int i = 0; i < nmax; i++) {
            a[i] = g_attns[r + i];
            m = fmaxf(m, a[i]);
        }
        float den = 0.f;
        for (int i = 0; i < nmax; i++) {
            float e = __expf(a[i] - m);
            ws[i] = e;
            den += e;
            invden[i] = 1.0f / den;
        }
    }
    asm volatile("cp.async.wait_group 0;\n" ::: "memory");
    __syncthreads();

    const float4* st4  = (const float4*)states;
    float4*       out4 = (float4*)out;

    const float4 s0 = st4[r * 256 + tid];
    float4 num = make_float4(0.f, 0.f, 0.f, 0.f);

    #pragma unroll
    for (int i = 0; i < MAXW; i++) {
        if (i < nmax) {
            const float  wv = ws[i];
            const float4 e  = ((const float4*)se[i])[tid];
            num.x += wv * e.x; num.y += wv * e.y;
            num.z += wv * e.z; num.w += wv * e.w;

            // section offset for width n=i+1: (n-1)*2049 - n(n-1)/2
            const int row  = i * (T_TOK + 1) - ((i + 1) * i) / 2 + r;
            const int base = row * 768;                // 3072 floats / 4

            const float4 send = st4[(r + i) * 256 + tid];
            const float  id   = invden[i];
            __stcs(&out4[base + tid],       s0);
            __stcs(&out4[base + 256 + tid], send);
            __stcs(&out4[base + 512 + tid],
                   make_float4(num.x * id, num.y * id, num.z * id, num.w * id));
        }
    }
}

// ---------------------------------------------------------------------------
extern "C" void kernel_launch(void* const* d_in, const int* in_sizes, int n_in,
                              void* d_out, int out_size) {
    const float* embeds = (const float*)d_in[0];
    const float* states = (const float*)d_in[1];
    const float* w1     = (const float*)d_in[2];
    const float* b1     = (const float*)d_in[3];
    const float* w2     = (const float*)d_in[4];
    const float* b2     = (const float*)d_in[5];
    const float* w3     = (const float*)d_in[6];
    const float* b3     = (const float*)d_in[7];
    float* out = (float*)d_out;

    mlp_kernel<<<T_TOK / TMM, MLPT>>>(states, w1, b1, w2, b2, w3, b3);
    assemble_kernel<<<T_TOK, 256>>>(embeds, states, out);
}